// round 1
// baseline (speedup 1.0000x reference)
#include <cuda_runtime.h>
#include <math.h>

#define Bsz 4
#define C 64
#define H 128
#define W 128
#define N 16384   // H*W per batch
#define OC 89

// scratch (allocations are forbidden; __device__ globals are allowed)
__device__ float g_lat_t[Bsz * N * C];   // latents channels-last  [b][p][c]
__device__ float g_qf[Bsz * N * C];      // bilinear-sampled features [b][n][c] (flat)
__device__ float g_kv[Bsz * N * 2 * C];  // per-position kv [b][p][128]

// ---------------------------------------------------------------------------
// K0: transpose latents [b][c][p] -> [b][p][c]
// ---------------------------------------------------------------------------
__global__ void k_transpose(const float* __restrict__ lat) {
    __shared__ float s[64][65];
    int b  = blockIdx.x >> 8;            // 256 p-blocks per batch
    int pb = (blockIdx.x & 255) * 64;
    int tid = threadIdx.x;
    const float* src = lat + (size_t)b * N * C;
    {
        int pq = tid & 63, cg = tid >> 6;
        #pragma unroll
        for (int k = 0; k < 16; k++) {
            int c = cg * 16 + k;
            s[c][pq] = src[(size_t)c * N + pb + pq];
        }
    }
    __syncthreads();
    float* dst = g_lat_t + (size_t)b * N * C;
    {
        int cl = tid & 63, pg = tid >> 6;
        #pragma unroll
        for (int k = 0; k < 16; k++) {
            int p = pg * 16 + k;
            dst[(size_t)(pb + p) * C + cl] = s[cl][p];
        }
    }
}

// ---------------------------------------------------------------------------
// K1: bilinear sample of latents at xy=flip(coords). One warp per point.
// ---------------------------------------------------------------------------
__global__ void k_sample_lat(const float* __restrict__ coords) {
    int gwarp = (blockIdx.x * blockDim.x + threadIdx.x) >> 5;
    int lane  = threadIdx.x & 31;
    if (gwarp >= Bsz * N) return;
    int b = gwarp >> 14;

    float y = coords[(size_t)gwarp * 2 + 0];   // xy = flip -> x = coords[...,1]
    float x = coords[(size_t)gwarp * 2 + 1];
    float ix = ((x + 1.f) * (float)W - 1.f) * 0.5f;
    float iy = ((y + 1.f) * (float)H - 1.f) * 0.5f;
    float x0f = floorf(ix), y0f = floorf(iy);
    float wx1 = ix - x0f, wy1 = iy - y0f;
    int x0 = (int)x0f, y0 = (int)y0f;

    const float* base = g_lat_t + (size_t)b * N * C;
    float2 acc = make_float2(0.f, 0.f);
    #pragma unroll
    for (int dy = 0; dy < 2; dy++) {
        #pragma unroll
        for (int dx = 0; dx < 2; dx++) {
            int xc = x0 + dx, yc = y0 + dy;
            float wgt = (dx ? wx1 : 1.f - wx1) * (dy ? wy1 : 1.f - wy1);
            bool valid = (xc >= 0) && (xc < W) && (yc >= 0) && (yc < H);
            int xi = min(max(xc, 0), W - 1);
            int yi = min(max(yc, 0), H - 1);
            float wv = valid ? wgt : 0.f;
            float2 t = ((const float2*)(base + ((size_t)yi * W + xi) * C))[lane];
            acc.x += wv * t.x;
            acc.y += wv * t.y;
        }
    }
    ((float2*)(g_qf + (size_t)gwarp * C))[lane] = acc;
}

// ---------------------------------------------------------------------------
// K2: per-position kv = LN_c(uf column) @ w_kv  -> g_kv[b][p][128]
//     uf column at p = g_qf flat (per batch) at [c*N + p]
//     64 positions / block, 256 threads (4 threads per position)
// ---------------------------------------------------------------------------
__global__ void k_kv(const float* __restrict__ w_kv,
                     const float* __restrict__ lnc_s,
                     const float* __restrict__ lnc_b) {
    __shared__ float xs[64][65];
    __shared__ float wkv[64 * 128];
    __shared__ float sc[64], sb[64];
    int b  = blockIdx.x >> 8;
    int pb = (blockIdx.x & 255) * 64;
    int tid = threadIdx.x;

    #pragma unroll
    for (int i = 0; i < 8; i++)
        ((float4*)wkv)[tid + i * 256] = ((const float4*)w_kv)[tid + i * 256];
    if (tid < 64) { sc[tid] = lnc_s[tid]; sb[tid] = lnc_b[tid]; }

    const float* qb = g_qf + (size_t)b * N * C;
    {
        int pq = tid & 63, cg = tid >> 6;
        #pragma unroll
        for (int k = 0; k < 16; k++) {
            int c = cg * 16 + k;
            xs[c][pq] = qb[(size_t)c * N + pb + pq];
        }
    }
    __syncthreads();

    int p = tid >> 2, sub = tid & 3;
    float sum = 0.f, sq = 0.f;
    #pragma unroll
    for (int k = 0; k < 16; k++) {
        float v = xs[sub * 16 + k][p];
        sum += v; sq += v * v;
    }
    sum += __shfl_xor_sync(~0u, sum, 1); sq += __shfl_xor_sync(~0u, sq, 1);
    sum += __shfl_xor_sync(~0u, sum, 2); sq += __shfl_xor_sync(~0u, sq, 2);
    float mu   = sum * (1.f / 64.f);
    float var  = sq * (1.f / 64.f) - mu * mu;
    float rstd = rsqrtf(var + 1e-5f);
    #pragma unroll
    for (int k = 0; k < 16; k++) {
        int c = sub * 16 + k;
        xs[c][p] = (xs[c][p] - mu) * rstd * sc[c] + sb[c];
    }
    __syncthreads();

    float acc[32];
    #pragma unroll
    for (int i = 0; i < 32; i++) acc[i] = 0.f;
    #pragma unroll 8
    for (int c = 0; c < 64; c++) {
        float xv = xs[c][p];
        const float4* wr = (const float4*)(wkv + c * 128 + sub * 32);
        #pragma unroll
        for (int k = 0; k < 8; k++) {
            float4 w4 = wr[k];
            acc[k * 4 + 0] += xv * w4.x;
            acc[k * 4 + 1] += xv * w4.y;
            acc[k * 4 + 2] += xv * w4.z;
            acc[k * 4 + 3] += xv * w4.w;
        }
    }
    float* o = g_kv + ((size_t)b * N + pb + p) * 128 + sub * 32;
    #pragma unroll
    for (int k = 0; k < 8; k++)
        ((float4*)o)[k] = make_float4(acc[k*4], acc[k*4+1], acc[k*4+2], acc[k*4+3]);
}

// ---------------------------------------------------------------------------
// K3: attention. One warp per query, 32 queries per warp (loop).
// ---------------------------------------------------------------------------
__global__ void k_attn(const float* __restrict__ w_q,
                       const float* __restrict__ w_out,
                       const float* __restrict__ b_out,
                       const float* __restrict__ lnq_s,
                       const float* __restrict__ lnq_b,
                       float* __restrict__ out) {
    __shared__ float wq[64 * 64], wo[64 * 64];
    __shared__ float bo[64], ls[64], lb[64];
    int tid = threadIdx.x;
    #pragma unroll
    for (int i = 0; i < 4; i++) {
        ((float4*)wq)[tid + i * 256] = ((const float4*)w_q)[tid + i * 256];
        ((float4*)wo)[tid + i * 256] = ((const float4*)w_out)[tid + i * 256];
    }
    if (tid < 64) { bo[tid] = b_out[tid]; ls[tid] = lnq_s[tid]; lb[tid] = lnq_b[tid]; }
    __syncthreads();

    int lane = tid & 31;
    int warp_global = (blockIdx.x * blockDim.x + tid) >> 5;   // 0..2047

    for (int it = 0; it < 32; it++) {
        int g = warp_global * 32 + it;
        int b = g >> 14, n = g & (N - 1);

        // LN_q of qf row
        float x0 = g_qf[(size_t)g * 64 + lane];
        float x1 = g_qf[(size_t)g * 64 + 32 + lane];
        float s = x0 + x1, sq = x0 * x0 + x1 * x1;
        #pragma unroll
        for (int o = 1; o < 32; o <<= 1) {
            s  += __shfl_xor_sync(~0u, s, o);
            sq += __shfl_xor_sync(~0u, sq, o);
        }
        float mu = s * (1.f / 64.f);
        float var = sq * (1.f / 64.f) - mu * mu;
        float rstd = rsqrtf(var + 1e-5f);
        float xq0 = (x0 - mu) * rstd * ls[lane]      + lb[lane];
        float xq1 = (x1 - mu) * rstd * ls[lane + 32] + lb[lane + 32];

        // q = xq @ w_q  (each lane owns outputs lane, lane+32)
        float q0 = 0.f, q1 = 0.f;
        #pragma unroll
        for (int c = 0; c < 32; c++) {
            float xv = __shfl_sync(~0u, xq0, c);
            q0 += xv * wq[c * 64 + lane];
            q1 += xv * wq[c * 64 + 32 + lane];
        }
        #pragma unroll
        for (int c = 0; c < 32; c++) {
            float xv = __shfl_sync(~0u, xq1, c);
            q0 += xv * wq[(c + 32) * 64 + lane];
            q1 += xv * wq[(c + 32) * 64 + 32 + lane];
        }

        // 9 neighbors: sim, softmax, weighted V
        int h = n >> 7, w = n & 127;
        const float* kvb = g_kv + (size_t)b * N * 128;
        int pp[9];
        float sim[9];
        #pragma unroll
        for (int k = 0; k < 9; k++) {
            int di = k / 3 - 1, dj = k % 3 - 1;
            int hh = min(max(h + di, 0), H - 1);
            int ww = min(max(w + dj, 0), W - 1);
            pp[k] = hh * W + ww;
            const float* kr = kvb + (size_t)pp[k] * 128;
            float part = q0 * kr[lane] + q1 * kr[32 + lane];
            #pragma unroll
            for (int o = 1; o < 32; o <<= 1) part += __shfl_xor_sync(~0u, part, o);
            sim[k] = part * 0.125f;
        }
        float m = sim[0];
        #pragma unroll
        for (int k = 1; k < 9; k++) m = fmaxf(m, sim[k]);
        float e[9], den = 0.f;
        #pragma unroll
        for (int k = 0; k < 9; k++) { e[k] = expf(sim[k] - m); den += e[k]; }
        float inv = 1.f / den;

        float o0 = 0.f, o1 = 0.f;
        #pragma unroll
        for (int k = 0; k < 9; k++) {
            const float* vr = kvb + (size_t)pp[k] * 128 + 64;
            float a = e[k] * inv;
            o0 += a * vr[lane];
            o1 += a * vr[32 + lane];
        }

        // out = o @ w_out + b_out
        float r0 = bo[lane], r1 = bo[32 + lane];
        #pragma unroll
        for (int c = 0; c < 32; c++) {
            float ov = __shfl_sync(~0u, o0, c);
            r0 += ov * wo[c * 64 + lane];
            r1 += ov * wo[c * 64 + 32 + lane];
        }
        #pragma unroll
        for (int c = 0; c < 32; c++) {
            float ov = __shfl_sync(~0u, o1, c);
            r0 += ov * wo[(c + 32) * 64 + lane];
            r1 += ov * wo[(c + 32) * 64 + 32 + lane];
        }
        out[(size_t)g * OC + lane]      = r0;
        out[(size_t)g * OC + 32 + lane] = r1;
    }
}

// ---------------------------------------------------------------------------
// K4: tail — image bilinear sample (1 ch, 256x256), analytic fcoord sample,
//     positional encoding. One thread per point -> out[..., 64:89]
// ---------------------------------------------------------------------------
__global__ void k_tail(const float* __restrict__ coords,
                       const float* __restrict__ image,
                       float* __restrict__ out) {
    int g = blockIdx.x * blockDim.x + threadIdx.x;
    if (g >= Bsz * N) return;
    int b = g >> 14;
    float y = coords[(size_t)g * 2 + 0];
    float x = coords[(size_t)g * 2 + 1];

    // image sample, 256x256
    float ix = ((x + 1.f) * 256.f - 1.f) * 0.5f;
    float iy = ((y + 1.f) * 256.f - 1.f) * 0.5f;
    float x0f = floorf(ix), y0f = floorf(iy);
    float wx = ix - x0f, wy = iy - y0f;
    int x0 = (int)x0f, y0 = (int)y0f;
    const float* img = image + (size_t)b * 256 * 256;

    // analytic fcoord sample, 128x128
    float ix2 = ((x + 1.f) * 128.f - 1.f) * 0.5f;
    float iy2 = ((y + 1.f) * 128.f - 1.f) * 0.5f;
    float x0f2 = floorf(ix2), y0f2 = floorf(iy2);
    float wx2 = ix2 - x0f2, wy2 = iy2 - y0f2;
    int x02 = (int)x0f2, y02 = (int)y0f2;

    float qin = 0.f, qcy = 0.f, qcx = 0.f;
    #pragma unroll
    for (int dy = 0; dy < 2; dy++) {
        #pragma unroll
        for (int dx = 0; dx < 2; dx++) {
            {
                int xc = x0 + dx, yc = y0 + dy;
                float wgt = (dx ? wx : 1.f - wx) * (dy ? wy : 1.f - wy);
                bool valid = (xc >= 0) && (xc < 256) && (yc >= 0) && (yc < 256);
                int xi = min(max(xc, 0), 255), yi = min(max(yc, 0), 255);
                qin += (valid ? wgt : 0.f) * img[yi * 256 + xi];
            }
            {
                int xc = x02 + dx, yc = y02 + dy;
                float wgt = (dx ? wx2 : 1.f - wx2) * (dy ? wy2 : 1.f - wy2);
                bool valid = (xc >= 0) && (xc < 128) && (yc >= 0) && (yc < 128);
                int xi = min(max(xc, 0), 127), yi = min(max(yc, 0), 127);
                float wv = valid ? wgt : 0.f;
                qcy += wv * (-1.f + (2.f * yi + 1.f) * (1.f / 128.f));
                qcx += wv * (-1.f + (2.f * xi + 1.f) * (1.f / 128.f));
            }
        }
    }

    float* o = out + (size_t)g * OC + 64;
    o[0] = qin;
    float cy = (qcy + 1.f) * 0.5f;
    float cx = (qcx + 1.f) * 0.5f;
    const float PI = 3.14159265358979323846f;
    #pragma unroll
    for (int k = 0; k < 6; k++) {
        float f = (float)(1 << k) * PI;
        float sy, cvy, sx, cvx;
        sincosf(cy * f, &sy, &cvy);
        sincosf(cx * f, &sx, &cvx);
        o[1 + k]          = sy;   // sin, dim 0 (y)
        o[1 + 6 + k]      = sx;   // sin, dim 1 (x)
        o[1 + 12 + k]     = cvy;  // cos, dim 0
        o[1 + 12 + 6 + k] = cvx;  // cos, dim 1
    }
}

extern "C" void kernel_launch(void* const* d_in, const int* in_sizes, int n_in,
                              void* d_out, int out_size) {
    const float* image   = (const float*)d_in[0];
    const float* latents = (const float*)d_in[1];
    const float* coords  = (const float*)d_in[2];
    const float* lnq_s   = (const float*)d_in[3];
    const float* lnq_b   = (const float*)d_in[4];
    const float* lnc_s   = (const float*)d_in[5];
    const float* lnc_b   = (const float*)d_in[6];
    const float* w_q     = (const float*)d_in[7];
    const float* w_kv    = (const float*)d_in[8];
    const float* w_out   = (const float*)d_in[9];
    const float* b_out   = (const float*)d_in[10];
    float* out = (float*)d_out;

    k_transpose <<<1024, 256>>>(latents);
    k_sample_lat<<<8192, 256>>>(coords);
    k_kv        <<<1024, 256>>>(w_kv, lnc_s, lnc_b);
    k_attn      <<<256, 256>>>(w_q, w_out, b_out, lnq_s, lnq_b, out);
    k_tail      <<<256, 256>>>(coords, image, out);
}

// round 2
// speedup vs baseline: 1.4669x; 1.4669x over previous
#include <cuda_runtime.h>
#include <math.h>

#define Bsz 4
#define C 64
#define H 128
#define W 128
#define N 16384   // H*W per batch
#define OC 89

// scratch (__device__ globals; allocation is forbidden)
__device__ float g_lat_t[Bsz * N * C];    // latents channels-last [b][p][c]
__device__ float g_qf[Bsz * N * C];       // bilinear-sampled features [b][n][c]
__device__ float g_qkvo[Bsz * N * 192];   // per row: q[0:64] | k[64:128] | vo[128:192]
__device__ float g_Wc[64 * 192];          // folded weights: y(64) -> q|k|vo(192)
__device__ float g_bc[192];               // folded bias

// ---------------- f32x2 helpers (sm_103a packed fp32) ----------------------
__device__ __forceinline__ void ffma2(unsigned long long& d,
                                      unsigned long long a,
                                      unsigned long long b) {
    asm("fma.rn.f32x2 %0, %1, %2, %0;" : "+l"(d) : "l"(a), "l"(b));
}
__device__ __forceinline__ unsigned long long f2_to_ull(float2 v) {
    unsigned long long r;
    asm("mov.b64 %0, {%1, %2};" : "=l"(r) : "f"(v.x), "f"(v.y));
    return r;
}
__device__ __forceinline__ unsigned long long dup_f32(float v) {
    unsigned long long r;
    asm("mov.b64 %0, {%1, %1};" : "=l"(r) : "f"(v));
    return r;
}
__device__ __forceinline__ float2 ull_to_f2(unsigned long long v) {
    float2 r;
    asm("mov.b64 {%0, %1}, %2;" : "=f"(r.x), "=f"(r.y) : "l"(v));
    return r;
}

// ---------------------------------------------------------------------------
// K0: transpose latents [b][c][p] -> [b][p][c]
// ---------------------------------------------------------------------------
__global__ void k_transpose(const float* __restrict__ lat) {
    __shared__ float s[64][65];
    int b  = blockIdx.x >> 8;
    int pb = (blockIdx.x & 255) * 64;
    int tid = threadIdx.x;
    const float* src = lat + (size_t)b * N * C;
    {
        int pq = tid & 63, cg = tid >> 6;
        #pragma unroll
        for (int k = 0; k < 16; k++) {
            int c = cg * 16 + k;
            s[c][pq] = src[(size_t)c * N + pb + pq];
        }
    }
    __syncthreads();
    float* dst = g_lat_t + (size_t)b * N * C;
    {
        int cl = tid & 63, pg = tid >> 6;
        #pragma unroll
        for (int k = 0; k < 16; k++) {
            int p = pg * 16 + k;
            dst[(size_t)(pb + p) * C + cl] = s[cl][p];
        }
    }
}

// ---------------------------------------------------------------------------
// K1: bilinear sample of latents. One warp per point.
// ---------------------------------------------------------------------------
__global__ void k_sample_lat(const float* __restrict__ coords) {
    int gwarp = (blockIdx.x * blockDim.x + threadIdx.x) >> 5;
    int lane  = threadIdx.x & 31;
    if (gwarp >= Bsz * N) return;
    int b = gwarp >> 14;

    float y = coords[(size_t)gwarp * 2 + 0];   // xy = flip(coords)
    float x = coords[(size_t)gwarp * 2 + 1];
    float ix = ((x + 1.f) * (float)W - 1.f) * 0.5f;
    float iy = ((y + 1.f) * (float)H - 1.f) * 0.5f;
    float x0f = floorf(ix), y0f = floorf(iy);
    float wx1 = ix - x0f, wy1 = iy - y0f;
    int x0 = (int)x0f, y0 = (int)y0f;

    const float* base = g_lat_t + (size_t)b * N * C;
    float2 acc = make_float2(0.f, 0.f);
    #pragma unroll
    for (int dy = 0; dy < 2; dy++) {
        #pragma unroll
        for (int dx = 0; dx < 2; dx++) {
            int xc = x0 + dx, yc = y0 + dy;
            float wgt = (dx ? wx1 : 1.f - wx1) * (dy ? wy1 : 1.f - wy1);
            bool valid = (xc >= 0) && (xc < W) && (yc >= 0) && (yc < H);
            int xi = min(max(xc, 0), W - 1);
            int yi = min(max(yc, 0), H - 1);
            float wv = valid ? wgt : 0.f;
            float2 t = ((const float2*)(base + ((size_t)yi * W + xi) * C))[lane];
            acc.x += wv * t.x;
            acc.y += wv * t.y;
        }
    }
    ((float2*)(g_qf + (size_t)gwarp * C))[lane] = acc;
}

// ---------------------------------------------------------------------------
// k_prep: fold LN scales into weights, build combined 64x192 matrix + bias.
//   cols 0:64   q : Wq'[c][j]  = lnq_s[c]*w_q[c][j]
//   cols 64:128 k : Wk'[c][j]  = lnc_s[c]*w_kv[c][j]
//   cols 128:192 vo: Wvo'[c][j] = lnc_s[c]*(w_kv[:,64:]@w_out)[c][j]
//   bias_j = sum_c ln_bias[c]*M[c][j]
// ---------------------------------------------------------------------------
__global__ void k_prep(const float* __restrict__ w_q,
                       const float* __restrict__ w_kv,
                       const float* __restrict__ w_out,
                       const float* __restrict__ lnq_s,
                       const float* __restrict__ lnq_b,
                       const float* __restrict__ lnc_s,
                       const float* __restrict__ lnc_b) {
    __shared__ float W2[64 * 64];
    int tid = threadIdx.x;
    for (int idx = tid; idx < 4096; idx += 256) {
        int c = idx >> 6, j = idx & 63;
        float s = 0.f;
        #pragma unroll 8
        for (int t = 0; t < 64; t++)
            s += w_kv[c * 128 + 64 + t] * w_out[t * 64 + j];
        W2[idx] = s;
    }
    __syncthreads();
    for (int idx = tid; idx < 64 * 192; idx += 256) {
        int c = idx / 192, j = idx % 192;
        float v;
        if (j < 64)       v = lnq_s[c] * w_q[c * 64 + j];
        else if (j < 128) v = lnc_s[c] * w_kv[c * 128 + (j - 64)];
        else              v = lnc_s[c] * W2[c * 64 + (j - 128)];
        g_Wc[idx] = v;
    }
    for (int j = tid; j < 192; j += 256) {
        float s = 0.f;
        if (j < 64) {
            for (int c = 0; c < 64; c++) s += lnq_b[c] * w_q[c * 64 + j];
        } else if (j < 128) {
            for (int c = 0; c < 64; c++) s += lnc_b[c] * w_kv[c * 128 + (j - 64)];
        } else {
            for (int c = 0; c < 64; c++) s += lnc_b[c] * W2[c * 64 + (j - 128)];
        }
        g_bc[j] = s;
    }
}

// ---------------------------------------------------------------------------
// K2: per position p (tile of 64 per block):
//   yq = normalize(qf row p)     (query-row LN, scale folded into weights)
//   yc = normalize(uf column p)  (ctx LN, uf = flat reinterpret of qf)
//   [q|k|vo](p) = [yq|yc|yc] @ g_Wc + g_bc   -> g_qkvo[b*N+p][192]
// 192 threads: og=tid%12 owns 16 outputs, pg=tid/12 owns 4 positions.
// ---------------------------------------------------------------------------
__global__ void k_qkvo() {
    __shared__ float yq[64 * 65];
    __shared__ float yc[64 * 65];
    int b  = blockIdx.x >> 8;           // 256 blocks per batch
    int pb = (blockIdx.x & 255) * 64;
    int tid = threadIdx.x;

    // load yq tile: rows of g_qf
    const float* qrow = g_qf + ((size_t)b * N + pb) * 64;
    for (int idx = tid; idx < 4096; idx += 192) {
        int p = idx >> 6, c = idx & 63;
        yq[p * 65 + c] = qrow[idx];
    }
    // load yc tile: columns of flat buffer (uf layout)
    const float* qb = g_qf + (size_t)b * N * 64;
    for (int idx = tid; idx < 4096; idx += 192) {
        int c = idx >> 6, p = idx & 63;
        yc[p * 65 + c] = qb[(size_t)c * N + pb + p];
    }
    __syncthreads();

    // LN (normalize only; scale/bias folded into weights)
    if (tid < 128) {
        float* row = ((tid < 64) ? yq : yc) + (tid & 63) * 65;
        float s = 0.f, sq = 0.f;
        #pragma unroll 8
        for (int c = 0; c < 64; c++) { float v = row[c]; s += v; sq += v * v; }
        float mu = s * (1.f / 64.f);
        float var = sq * (1.f / 64.f) - mu * mu;
        float rstd = rsqrtf(var + 1e-5f);
        #pragma unroll 8
        for (int c = 0; c < 64; c++) row[c] = (row[c] - mu) * rstd;
    }
    __syncthreads();

    int og = tid % 12;          // output group: 16 outputs
    int pg = tid / 12;          // position group: 4 positions
    int j0 = og * 16;
    const float* ybuf = (og < 4) ? yq : yc;

    unsigned long long acc[4][8];
    #pragma unroll
    for (int k = 0; k < 8; k++) {
        unsigned long long bv = f2_to_ull(__ldg((const float2*)&g_bc[j0 + 2 * k]));
        #pragma unroll
        for (int i = 0; i < 4; i++) acc[i][k] = bv;
    }

    #pragma unroll 2
    for (int c = 0; c < 64; c++) {
        unsigned long long w[8];
        #pragma unroll
        for (int k = 0; k < 8; k++)
            w[k] = f2_to_ull(__ldg((const float2*)&g_Wc[c * 192 + j0 + 2 * k]));
        #pragma unroll
        for (int i = 0; i < 4; i++) {
            unsigned long long yy = dup_f32(ybuf[(pg * 4 + i) * 65 + c]);
            #pragma unroll
            for (int k = 0; k < 8; k++) ffma2(acc[i][k], w[k], yy);
        }
    }

    #pragma unroll
    for (int i = 0; i < 4; i++) {
        float* o = g_qkvo + ((size_t)b * N + pb + pg * 4 + i) * 192 + j0;
        #pragma unroll
        for (int k = 0; k < 8; k++)
            ((float2*)o)[k] = ull_to_f2(acc[i][k]);
    }
}

// ---------------------------------------------------------------------------
// K3: attention gather. One warp per query, 8 adjacent queries per block.
// ---------------------------------------------------------------------------
__global__ void k_attn(const float* __restrict__ b_out,
                       float* __restrict__ out) {
    int lane = threadIdx.x & 31;
    int g = blockIdx.x * 8 + (threadIdx.x >> 5);   // 0..65535
    int b = g >> 14, n = g & (N - 1);
    int h = n >> 7, w = n & 127;

    const float* row = g_qkvo + (size_t)g * 192;
    float q0 = row[lane], q1 = row[32 + lane];

    const float* kvb = g_qkvo + (size_t)b * N * 192;
    int pp[9];
    float e[9];
    #pragma unroll
    for (int k = 0; k < 9; k++) {
        int di = k / 3 - 1, dj = k % 3 - 1;
        int hh = min(max(h + di, 0), H - 1);
        int ww = min(max(w + dj, 0), W - 1);
        pp[k] = hh * W + ww;
        const float* kr = kvb + (size_t)pp[k] * 192 + 64;
        float part = q0 * kr[lane] + q1 * kr[32 + lane];
        #pragma unroll
        for (int o = 1; o < 32; o <<= 1) part += __shfl_xor_sync(~0u, part, o);
        e[k] = part * 0.125f;
    }
    float m = e[0];
    #pragma unroll
    for (int k = 1; k < 9; k++) m = fmaxf(m, e[k]);
    float den = 0.f;
    #pragma unroll
    for (int k = 0; k < 9; k++) { e[k] = __expf(e[k] - m); den += e[k]; }
    float inv = 1.f / den;

    float o0 = 0.f, o1 = 0.f;
    #pragma unroll
    for (int k = 0; k < 9; k++) {
        const float* vr = kvb + (size_t)pp[k] * 192 + 128;
        float a = e[k] * inv;
        o0 += a * vr[lane];
        o1 += a * vr[32 + lane];
    }
    out[(size_t)g * OC + lane]      = o0 + __ldg(&b_out[lane]);
    out[(size_t)g * OC + 32 + lane] = o1 + __ldg(&b_out[lane + 32]);
}

// ---------------------------------------------------------------------------
// K4: tail — image sample, analytic fcoord sample, positional encoding.
// ---------------------------------------------------------------------------
__global__ void k_tail(const float* __restrict__ coords,
                       const float* __restrict__ image,
                       float* __restrict__ out) {
    int g = blockIdx.x * blockDim.x + threadIdx.x;
    if (g >= Bsz * N) return;
    int b = g >> 14;
    float y = coords[(size_t)g * 2 + 0];
    float x = coords[(size_t)g * 2 + 1];

    float ix = ((x + 1.f) * 256.f - 1.f) * 0.5f;
    float iy = ((y + 1.f) * 256.f - 1.f) * 0.5f;
    float x0f = floorf(ix), y0f = floorf(iy);
    float wx = ix - x0f, wy = iy - y0f;
    int x0 = (int)x0f, y0 = (int)y0f;
    const float* img = image + (size_t)b * 256 * 256;

    float ix2 = ((x + 1.f) * 128.f - 1.f) * 0.5f;
    float iy2 = ((y + 1.f) * 128.f - 1.f) * 0.5f;
    float x0f2 = floorf(ix2), y0f2 = floorf(iy2);
    float wx2 = ix2 - x0f2, wy2 = iy2 - y0f2;
    int x02 = (int)x0f2, y02 = (int)y0f2;

    float qin = 0.f, qcy = 0.f, qcx = 0.f;
    #pragma unroll
    for (int dy = 0; dy < 2; dy++) {
        #pragma unroll
        for (int dx = 0; dx < 2; dx++) {
            {
                int xc = x0 + dx, yc = y0 + dy;
                float wgt = (dx ? wx : 1.f - wx) * (dy ? wy : 1.f - wy);
                bool valid = (xc >= 0) && (xc < 256) && (yc >= 0) && (yc < 256);
                int xi = min(max(xc, 0), 255), yi = min(max(yc, 0), 255);
                qin += (valid ? wgt : 0.f) * img[yi * 256 + xi];
            }
            {
                int xc = x02 + dx, yc = y02 + dy;
                float wgt = (dx ? wx2 : 1.f - wx2) * (dy ? wy2 : 1.f - wy2);
                bool valid = (xc >= 0) && (xc < 128) && (yc >= 0) && (yc < 128);
                int xi = min(max(xc, 0), 127), yi = min(max(yc, 0), 127);
                float wv = valid ? wgt : 0.f;
                qcy += wv * (-1.f + (2.f * yi + 1.f) * (1.f / 128.f));
                qcx += wv * (-1.f + (2.f * xi + 1.f) * (1.f / 128.f));
            }
        }
    }

    float* o = out + (size_t)g * OC + 64;
    o[0] = qin;
    float cy = (qcy + 1.f) * 0.5f;
    float cx = (qcx + 1.f) * 0.5f;
    const float PI = 3.14159265358979323846f;
    #pragma unroll
    for (int k = 0; k < 6; k++) {
        float f = (float)(1 << k) * PI;
        float sy, cvy, sx, cvx;
        sincosf(cy * f, &sy, &cvy);
        sincosf(cx * f, &sx, &cvx);
        o[1 + k]          = sy;
        o[1 + 6 + k]      = sx;
        o[1 + 12 + k]     = cvy;
        o[1 + 12 + 6 + k] = cvx;
    }
}

extern "C" void kernel_launch(void* const* d_in, const int* in_sizes, int n_in,
                              void* d_out, int out_size) {
    const float* image   = (const float*)d_in[0];
    const float* latents = (const float*)d_in[1];
    const float* coords  = (const float*)d_in[2];
    const float* lnq_s   = (const float*)d_in[3];
    const float* lnq_b   = (const float*)d_in[4];
    const float* lnc_s   = (const float*)d_in[5];
    const float* lnc_b   = (const float*)d_in[6];
    const float* w_q     = (const float*)d_in[7];
    const float* w_kv    = (const float*)d_in[8];
    const float* w_out   = (const float*)d_in[9];
    const float* b_out   = (const float*)d_in[10];
    float* out = (float*)d_out;

    k_prep      <<<1, 256>>>(w_q, w_kv, w_out, lnq_s, lnq_b, lnc_s, lnc_b);
    k_transpose <<<1024, 256>>>(latents);
    k_sample_lat<<<8192, 256>>>(coords);
    k_qkvo      <<<1024, 192>>>();
    k_attn      <<<8192, 256>>>(b_out, out);
    k_tail      <<<256, 256>>>(coords, image, out);
}

// round 3
// speedup vs baseline: 2.1052x; 1.4351x over previous
#include <cuda_runtime.h>
#include <math.h>

#define Bsz 4
#define C 64
#define H 128
#define W 128
#define N 16384   // H*W per batch
#define OC 89
#define YPAD 68   // [c][p] tile pitch: 68*4 bytes = 16B-aligned rows, low-conflict

// scratch (__device__ globals; allocation is forbidden)
__device__ float g_lat_t[Bsz * N * C];    // latents channels-last [b][p][c]
__device__ float g_qf[Bsz * N * C];       // bilinear-sampled features [b][n][c]
__device__ float g_qkvo[Bsz * N * 192];   // per row: q[0:64] | k[64:128] | vo[128:192]
__device__ float g_Wc[64 * 192];          // folded weights: y(64) -> q|k|vo(192)
__device__ float g_bc[192];               // folded bias

// ---------------- f32x2 helpers (sm_103a packed fp32) ----------------------
__device__ __forceinline__ void ffma2(unsigned long long& d,
                                      unsigned long long a,
                                      unsigned long long b) {
    asm("fma.rn.f32x2 %0, %1, %2, %0;" : "+l"(d) : "l"(a), "l"(b));
}
__device__ __forceinline__ unsigned long long f2_to_ull(float x, float y) {
    unsigned long long r;
    asm("mov.b64 %0, {%1, %2};" : "=l"(r) : "f"(x), "f"(y));
    return r;
}
__device__ __forceinline__ unsigned long long dup_f32(float v) {
    unsigned long long r;
    asm("mov.b64 %0, {%1, %1};" : "=l"(r) : "f"(v));
    return r;
}
__device__ __forceinline__ float2 ull_to_f2(unsigned long long v) {
    float2 r;
    asm("mov.b64 {%0, %1}, %2;" : "=f"(r.x), "=f"(r.y) : "l"(v));
    return r;
}

// ---------------------------------------------------------------------------
// K0: transpose latents [b][c][p] -> [b][p][c]
// ---------------------------------------------------------------------------
__global__ void k_transpose(const float* __restrict__ lat) {
    __shared__ float s[64][65];
    int b  = blockIdx.x >> 8;
    int pb = (blockIdx.x & 255) * 64;
    int tid = threadIdx.x;
    const float* src = lat + (size_t)b * N * C;
    {
        int pq = tid & 63, cg = tid >> 6;
        #pragma unroll
        for (int k = 0; k < 16; k++) {
            int c = cg * 16 + k;
            s[c][pq] = src[(size_t)c * N + pb + pq];
        }
    }
    __syncthreads();
    float* dst = g_lat_t + (size_t)b * N * C;
    {
        int cl = tid & 63, pg = tid >> 6;
        #pragma unroll
        for (int k = 0; k < 16; k++) {
            int p = pg * 16 + k;
            dst[(size_t)(pb + p) * C + cl] = s[cl][p];
        }
    }
}

// ---------------------------------------------------------------------------
// K1: bilinear sample of latents. One warp per point.
// ---------------------------------------------------------------------------
__global__ void k_sample_lat(const float* __restrict__ coords) {
    int gwarp = (blockIdx.x * blockDim.x + threadIdx.x) >> 5;
    int lane  = threadIdx.x & 31;
    if (gwarp >= Bsz * N) return;
    int b = gwarp >> 14;

    float y = coords[(size_t)gwarp * 2 + 0];   // xy = flip(coords)
    float x = coords[(size_t)gwarp * 2 + 1];
    float ix = ((x + 1.f) * (float)W - 1.f) * 0.5f;
    float iy = ((y + 1.f) * (float)H - 1.f) * 0.5f;
    float x0f = floorf(ix), y0f = floorf(iy);
    float wx1 = ix - x0f, wy1 = iy - y0f;
    int x0 = (int)x0f, y0 = (int)y0f;

    const float* base = g_lat_t + (size_t)b * N * C;
    float2 acc = make_float2(0.f, 0.f);
    #pragma unroll
    for (int dy = 0; dy < 2; dy++) {
        #pragma unroll
        for (int dx = 0; dx < 2; dx++) {
            int xc = x0 + dx, yc = y0 + dy;
            float wgt = (dx ? wx1 : 1.f - wx1) * (dy ? wy1 : 1.f - wy1);
            bool valid = (xc >= 0) && (xc < W) && (yc >= 0) && (yc < H);
            int xi = min(max(xc, 0), W - 1);
            int yi = min(max(yc, 0), H - 1);
            float wv = valid ? wgt : 0.f;
            float2 t = ((const float2*)(base + ((size_t)yi * W + xi) * C))[lane];
            acc.x += wv * t.x;
            acc.y += wv * t.y;
        }
    }
    ((float2*)(g_qf + (size_t)gwarp * C))[lane] = acc;
}

// ---------------------------------------------------------------------------
// k_prep: fold LN scales into weights, build combined 64x192 matrix + bias.
// ---------------------------------------------------------------------------
__global__ void k_prep(const float* __restrict__ w_q,
                       const float* __restrict__ w_kv,
                       const float* __restrict__ w_out,
                       const float* __restrict__ lnq_s,
                       const float* __restrict__ lnq_b,
                       const float* __restrict__ lnc_s,
                       const float* __restrict__ lnc_b) {
    __shared__ float W2[64 * 64];
    int tid = threadIdx.x;
    for (int idx = tid; idx < 4096; idx += 256) {
        int c = idx >> 6, j = idx & 63;
        float s = 0.f;
        #pragma unroll 8
        for (int t = 0; t < 64; t++)
            s += w_kv[c * 128 + 64 + t] * w_out[t * 64 + j];
        W2[idx] = s;
    }
    __syncthreads();
    for (int idx = tid; idx < 64 * 192; idx += 256) {
        int c = idx / 192, j = idx % 192;
        float v;
        if (j < 64)       v = lnq_s[c] * w_q[c * 64 + j];
        else if (j < 128) v = lnc_s[c] * w_kv[c * 128 + (j - 64)];
        else              v = lnc_s[c] * W2[c * 64 + (j - 128)];
        g_Wc[idx] = v;
    }
    for (int j = tid; j < 192; j += 256) {
        float s = 0.f;
        if (j < 64) {
            for (int c = 0; c < 64; c++) s += lnq_b[c] * w_q[c * 64 + j];
        } else if (j < 128) {
            for (int c = 0; c < 64; c++) s += lnc_b[c] * w_kv[c * 128 + (j - 64)];
        } else {
            for (int c = 0; c < 64; c++) s += lnc_b[c] * W2[c * 64 + (j - 128)];
        }
        g_bc[j] = s;
    }
}

// ---------------------------------------------------------------------------
// K2: qkvo GEMV, restructured.
//   y tiles stored [c][p] (pitch YPAD). yc needs NO transpose (flat uf column
//   read is already [c][p]). Warp = 32 cols x 32 positions; f32x2 packs two
//   POSITIONS so LDS.128 yields two ready operands; weight = scalar dup.
// ---------------------------------------------------------------------------
__global__ void __launch_bounds__(384) k_qkvo() {
    __shared__ float yq[64 * YPAD];
    __shared__ float yc[64 * YPAD];
    int b  = blockIdx.x >> 8;           // 256 blocks per batch
    int pb = (blockIdx.x & 255) * 64;
    int tid = threadIdx.x;

    // yq tile: global rows [p][c] -> smem [c][p]
    const float* qrow = g_qf + ((size_t)b * N + pb) * 64;
    for (int idx = tid; idx < 4096; idx += 384) {
        int p = idx >> 6, c = idx & 63;
        yq[c * YPAD + p] = qrow[idx];
    }
    // yc tile: flat columns, already [c][p]
    const float* qb = g_qf + (size_t)b * N * 64;
    for (int idx = tid; idx < 4096; idx += 384) {
        int c = idx >> 6, p = idx & 63;
        yc[c * YPAD + p] = qb[(size_t)c * N + pb + p];
    }
    __syncthreads();

    // LN (normalize only; scale/bias folded into weights). Thread-per-position,
    // lockstep c loop -> conflict-free smem columns.
    if (tid < 128) {
        float* col = ((tid < 64) ? yq : yc) + (tid & 63);
        float s = 0.f, sq = 0.f;
        #pragma unroll 8
        for (int c = 0; c < 64; c++) { float v = col[c * YPAD]; s += v; sq += v * v; }
        float mu = s * (1.f / 64.f);
        float var = sq * (1.f / 64.f) - mu * mu;
        float rstd = rsqrtf(var + 1e-5f);
        #pragma unroll 8
        for (int c = 0; c < 64; c++) col[c * YPAD] = (col[c * YPAD] - mu) * rstd;
    }
    __syncthreads();

    int warp = tid >> 5;        // 0..11
    int lane = tid & 31;
    int cg = warp % 6;          // column group: 32 cols
    int pg = warp / 6;          // 0..1 -> 32 positions
    int j  = cg * 32 + lane;
    int p0 = pg * 32;
    const float* ybuf = (cg < 2) ? yq : yc;   // cols 0:64 = q (yq); rest k/vo (yc)

    unsigned long long acc[16];
    {
        unsigned long long bdup = dup_f32(__ldg(&g_bc[j]));
        #pragma unroll
        for (int i = 0; i < 16; i++) acc[i] = bdup;
    }

    #pragma unroll 4
    for (int c = 0; c < 64; c++) {
        unsigned long long wv = dup_f32(__ldg(&g_Wc[c * 192 + j]));
        const float4* yp = (const float4*)&ybuf[c * YPAD + p0];
        #pragma unroll
        for (int k = 0; k < 8; k++) {
            float4 y4 = yp[k];
            ffma2(acc[2 * k],     f2_to_ull(y4.x, y4.y), wv);
            ffma2(acc[2 * k + 1], f2_to_ull(y4.z, y4.w), wv);
        }
    }

    float* ob = g_qkvo + ((size_t)b * N + pb + p0) * 192 + j;
    #pragma unroll
    for (int i = 0; i < 16; i++) {
        float2 v = ull_to_f2(acc[i]);
        ob[(size_t)(2 * i) * 192]     = v.x;
        ob[(size_t)(2 * i + 1) * 192] = v.y;
    }
}

// ---------------------------------------------------------------------------
// K3: attention gather. One warp per query, 8 adjacent queries per block.
// ---------------------------------------------------------------------------
__global__ void k_attn(const float* __restrict__ b_out,
                       float* __restrict__ out) {
    int lane = threadIdx.x & 31;
    int g = blockIdx.x * 8 + (threadIdx.x >> 5);   // 0..65535
    int b = g >> 14, n = g & (N - 1);
    int h = n >> 7, w = n & 127;

    const float* row = g_qkvo + (size_t)g * 192;
    float q0 = row[lane], q1 = row[32 + lane];

    const float* kvb = g_qkvo + (size_t)b * N * 192;
    int pp[9];
    float e[9];
    #pragma unroll
    for (int k = 0; k < 9; k++) {
        int di = k / 3 - 1, dj = k % 3 - 1;
        int hh = min(max(h + di, 0), H - 1);
        int ww = min(max(w + dj, 0), W - 1);
        pp[k] = hh * W + ww;
        const float* kr = kvb + (size_t)pp[k] * 192 + 64;
        float part = q0 * kr[lane] + q1 * kr[32 + lane];
        #pragma unroll
        for (int o = 1; o < 32; o <<= 1) part += __shfl_xor_sync(~0u, part, o);
        e[k] = part * 0.125f;
    }
    float m = e[0];
    #pragma unroll
    for (int k = 1; k < 9; k++) m = fmaxf(m, e[k]);
    float den = 0.f;
    #pragma unroll
    for (int k = 0; k < 9; k++) { e[k] = __expf(e[k] - m); den += e[k]; }
    float inv = 1.f / den;

    float o0 = 0.f, o1 = 0.f;
    #pragma unroll
    for (int k = 0; k < 9; k++) {
        const float* vr = kvb + (size_t)pp[k] * 192 + 128;
        float a = e[k] * inv;
        o0 += a * vr[lane];
        o1 += a * vr[32 + lane];
    }
    out[(size_t)g * OC + lane]      = o0 + __ldg(&b_out[lane]);
    out[(size_t)g * OC + 32 + lane] = o1 + __ldg(&b_out[lane + 32]);
}

// ---------------------------------------------------------------------------
// K4: tail — image sample, analytic fcoord sample, positional encoding.
// ---------------------------------------------------------------------------
__global__ void k_tail(const float* __restrict__ coords,
                       const float* __restrict__ image,
                       float* __restrict__ out) {
    int g = blockIdx.x * blockDim.x + threadIdx.x;
    if (g >= Bsz * N) return;
    int b = g >> 14;
    float y = coords[(size_t)g * 2 + 0];
    float x = coords[(size_t)g * 2 + 1];

    float ix = ((x + 1.f) * 256.f - 1.f) * 0.5f;
    float iy = ((y + 1.f) * 256.f - 1.f) * 0.5f;
    float x0f = floorf(ix), y0f = floorf(iy);
    float wx = ix - x0f, wy = iy - y0f;
    int x0 = (int)x0f, y0 = (int)y0f;
    const float* img = image + (size_t)b * 256 * 256;

    float ix2 = ((x + 1.f) * 128.f - 1.f) * 0.5f;
    float iy2 = ((y + 1.f) * 128.f - 1.f) * 0.5f;
    float x0f2 = floorf(ix2), y0f2 = floorf(iy2);
    float wx2 = ix2 - x0f2, wy2 = iy2 - y0f2;
    int x02 = (int)x0f2, y02 = (int)y0f2;

    float qin = 0.f, qcy = 0.f, qcx = 0.f;
    #pragma unroll
    for (int dy = 0; dy < 2; dy++) {
        #pragma unroll
        for (int dx = 0; dx < 2; dx++) {
            {
                int xc = x0 + dx, yc = y0 + dy;
                float wgt = (dx ? wx : 1.f - wx) * (dy ? wy : 1.f - wy);
                bool valid = (xc >= 0) && (xc < 256) && (yc >= 0) && (yc < 256);
                int xi = min(max(xc, 0), 255), yi = min(max(yc, 0), 255);
                qin += (valid ? wgt : 0.f) * img[yi * 256 + xi];
            }
            {
                int xc = x02 + dx, yc = y02 + dy;
                float wgt = (dx ? wx2 : 1.f - wx2) * (dy ? wy2 : 1.f - wy2);
                bool valid = (xc >= 0) && (xc < 128) && (yc >= 0) && (yc < 128);
                int xi = min(max(xc, 0), 127), yi = min(max(yc, 0), 127);
                float wv = valid ? wgt : 0.f;
                qcy += wv * (-1.f + (2.f * yi + 1.f) * (1.f / 128.f));
                qcx += wv * (-1.f + (2.f * xi + 1.f) * (1.f / 128.f));
            }
        }
    }

    float* o = out + (size_t)g * OC + 64;
    o[0] = qin;
    float cy = (qcy + 1.f) * 0.5f;
    float cx = (qcx + 1.f) * 0.5f;
    const float PI = 3.14159265358979323846f;
    #pragma unroll
    for (int k = 0; k < 6; k++) {
        float f = (float)(1 << k) * PI;
        float sy, cvy, sx, cvx;
        sincosf(cy * f, &sy, &cvy);
        sincosf(cx * f, &sx, &cvx);
        o[1 + k]          = sy;
        o[1 + 6 + k]      = sx;
        o[1 + 12 + k]     = cvy;
        o[1 + 12 + 6 + k] = cvx;
    }
}

extern "C" void kernel_launch(void* const* d_in, const int* in_sizes, int n_in,
                              void* d_out, int out_size) {
    const float* image   = (const float*)d_in[0];
    const float* latents = (const float*)d_in[1];
    const float* coords  = (const float*)d_in[2];
    const float* lnq_s   = (const float*)d_in[3];
    const float* lnq_b   = (const float*)d_in[4];
    const float* lnc_s   = (const float*)d_in[5];
    const float* lnc_b   = (const float*)d_in[6];
    const float* w_q     = (const float*)d_in[7];
    const float* w_kv    = (const float*)d_in[8];
    const float* w_out   = (const float*)d_in[9];
    const float* b_out   = (const float*)d_in[10];
    float* out = (float*)d_out;

    k_prep      <<<1, 256>>>(w_q, w_kv, w_out, lnq_s, lnq_b, lnc_s, lnc_b);
    k_transpose <<<1024, 256>>>(latents);
    k_sample_lat<<<8192, 256>>>(coords);
    k_qkvo      <<<1024, 384>>>();
    k_attn      <<<8192, 256>>>(b_out, out);
    k_tail      <<<256, 256>>>(coords, image, out);
}

// round 4
// speedup vs baseline: 3.5876x; 1.7041x over previous
#include <cuda_runtime.h>
#include <math.h>

#define Bsz 4
#define C 64
#define H 128
#define W 128
#define N 16384   // H*W per batch
#define OC 89
#define YPAD 68   // [c][p] tile pitch (floats); multiple of 4 -> float4 aligned

// scratch (__device__ globals; allocation is forbidden)
__device__ float g_lat_t[Bsz * N * C];    // latents channels-last [b][p][c]
__device__ float g_qf[Bsz * N * C];       // bilinear-sampled features [b][n][c]
__device__ float g_qkvo[Bsz * N * 192];   // per row: q[0:64] | k[64:128] | vo[128:192]
// folded weights, chunk-interleaved: g_Wt2[(c>>2)*192*4 + j*4 + (c&3)] = W'[c][j]
__device__ float g_Wt2[16 * 192 * 4];
__device__ float g_bc[192];               // folded bias

// ---------------- f32x2 helpers (sm_103a packed fp32) ----------------------
__device__ __forceinline__ void ffma2(unsigned long long& d,
                                      unsigned long long a,
                                      unsigned long long b) {
    asm("fma.rn.f32x2 %0, %1, %2, %0;" : "+l"(d) : "l"(a), "l"(b));
}
__device__ __forceinline__ unsigned long long f2_to_ull(float x, float y) {
    unsigned long long r;
    asm("mov.b64 %0, {%1, %2};" : "=l"(r) : "f"(x), "f"(y));
    return r;
}
__device__ __forceinline__ unsigned long long dup_f32(float v) {
    unsigned long long r;
    asm("mov.b64 %0, {%1, %1};" : "=l"(r) : "f"(v));
    return r;
}
__device__ __forceinline__ float2 ull_to_f2(unsigned long long v) {
    float2 r;
    asm("mov.b64 {%0, %1}, %2;" : "=f"(r.x), "=f"(r.y) : "l"(v));
    return r;
}

// ---------------------------------------------------------------------------
// K0: transpose latents [b][c][p] -> [b][p][c]
// ---------------------------------------------------------------------------
__global__ void k_transpose(const float* __restrict__ lat) {
    __shared__ float s[64][65];
    int b  = blockIdx.x >> 8;
    int pb = (blockIdx.x & 255) * 64;
    int tid = threadIdx.x;
    const float* src = lat + (size_t)b * N * C;
    {
        int pq = tid & 63, cg = tid >> 6;
        #pragma unroll
        for (int k = 0; k < 16; k++) {
            int c = cg * 16 + k;
            s[c][pq] = src[(size_t)c * N + pb + pq];
        }
    }
    __syncthreads();
    float* dst = g_lat_t + (size_t)b * N * C;
    {
        int cl = tid & 63, pg = tid >> 6;
        #pragma unroll
        for (int k = 0; k < 16; k++) {
            int p = pg * 16 + k;
            dst[(size_t)(pb + p) * C + cl] = s[cl][p];
        }
    }
}

// ---------------------------------------------------------------------------
// K1: bilinear sample of latents. One warp per point.
// ---------------------------------------------------------------------------
__global__ void k_sample_lat(const float* __restrict__ coords) {
    int gwarp = (blockIdx.x * blockDim.x + threadIdx.x) >> 5;
    int lane  = threadIdx.x & 31;
    if (gwarp >= Bsz * N) return;
    int b = gwarp >> 14;

    float y = coords[(size_t)gwarp * 2 + 0];   // xy = flip(coords)
    float x = coords[(size_t)gwarp * 2 + 1];
    float ix = ((x + 1.f) * (float)W - 1.f) * 0.5f;
    float iy = ((y + 1.f) * (float)H - 1.f) * 0.5f;
    float x0f = floorf(ix), y0f = floorf(iy);
    float wx1 = ix - x0f, wy1 = iy - y0f;
    int x0 = (int)x0f, y0 = (int)y0f;

    const float* base = g_lat_t + (size_t)b * N * C;
    float2 acc = make_float2(0.f, 0.f);
    #pragma unroll
    for (int dy = 0; dy < 2; dy++) {
        #pragma unroll
        for (int dx = 0; dx < 2; dx++) {
            int xc = x0 + dx, yc = y0 + dy;
            float wgt = (dx ? wx1 : 1.f - wx1) * (dy ? wy1 : 1.f - wy1);
            bool valid = (xc >= 0) && (xc < W) && (yc >= 0) && (yc < H);
            int xi = min(max(xc, 0), W - 1);
            int yi = min(max(yc, 0), H - 1);
            float wv = valid ? wgt : 0.f;
            float2 t = ((const float2*)(base + ((size_t)yi * W + xi) * C))[lane];
            acc.x += wv * t.x;
            acc.y += wv * t.y;
        }
    }
    ((float2*)(g_qf + (size_t)gwarp * C))[lane] = acc;
}

// ---------------------------------------------------------------------------
// k_prep: one block per output column j (192 blocks, 64 threads).
//   M[c][j]: j<64 -> w_q ; j<128 -> w_kv[:, j-64] ; j>=128 -> (w_kv[:,64:]@w_out)[:, j-128]
//   g_Wt2[(c>>2)*768 + j*4 + (c&3)] = lnX_s[c] * M[c][j]
//   g_bc[j] = sum_c lnX_b[c] * M[c][j]
// ---------------------------------------------------------------------------
__global__ void k_prep(const float* __restrict__ w_q,
                       const float* __restrict__ w_kv,
                       const float* __restrict__ w_out,
                       const float* __restrict__ lnq_s,
                       const float* __restrict__ lnq_b,
                       const float* __restrict__ lnc_s,
                       const float* __restrict__ lnc_b) {
    __shared__ float red[64];
    int j = blockIdx.x;
    int c = threadIdx.x;    // 0..63

    float m;
    float lns, lnb;
    if (j < 64) {
        m = w_q[c * 64 + j];
        lns = lnq_s[c]; lnb = lnq_b[c];
    } else if (j < 128) {
        m = w_kv[c * 128 + (j - 64)];
        lns = lnc_s[c]; lnb = lnc_b[c];
    } else {
        float s = 0.f;
        int jj = j - 128;
        #pragma unroll 8
        for (int t = 0; t < 64; t++)
            s += w_kv[c * 128 + 64 + t] * w_out[t * 64 + jj];
        m = s;
        lns = lnc_s[c]; lnb = lnc_b[c];
    }
    g_Wt2[(c >> 2) * 768 + j * 4 + (c & 3)] = lns * m;

    red[c] = lnb * m;
    __syncthreads();
    if (c < 32) {
        float v = red[c] + red[c + 32];
        #pragma unroll
        for (int o = 16; o > 0; o >>= 1) v += __shfl_xor_sync(~0u, v, o);
        if (c == 0) g_bc[j] = v;
    }
}

// ---------------------------------------------------------------------------
// K2: qkvo GEMM.  Block = 192 threads (6 warps), 64 positions.
//   Warp tile: 64 columns (lane j, j+32) x 32 positions (f32x2-packed).
//   wg = warp%3 picks column group (0->q uses yq; 1,2->k,vo use yc),
//   pg = warp/3 picks position half.
//   Per c: 8 broadcast LDS.128 (y) + 2 dup + 32 FFMA2; weights via one
//   coalesced LDG.128 per 4 c's per column.
// ---------------------------------------------------------------------------
__global__ void __launch_bounds__(192, 3) k_qkvo() {
    __shared__ float yq[64 * YPAD];
    __shared__ float yc[64 * YPAD];
    int b  = blockIdx.x >> 8;           // 256 blocks per batch
    int pb = (blockIdx.x & 255) * 64;
    int tid = threadIdx.x;

    // yq tile: global rows [p][c] -> smem [c][p]
    const float* qrow = g_qf + ((size_t)b * N + pb) * 64;
    for (int idx = tid; idx < 4096; idx += 192) {
        int p = idx >> 6, c = idx & 63;
        yq[c * YPAD + p] = qrow[idx];
    }
    // yc tile: flat columns, already [c][p]
    const float* qb = g_qf + (size_t)b * N * 64;
    for (int idx = tid; idx < 4096; idx += 192) {
        int c = idx >> 6, p = idx & 63;
        yc[c * YPAD + p] = qb[(size_t)c * N + pb + p];
    }
    __syncthreads();

    // LN (normalize only; scale/bias folded into weights)
    if (tid < 128) {
        float* col = ((tid < 64) ? yq : yc) + (tid & 63);
        float s = 0.f, sq = 0.f;
        #pragma unroll 8
        for (int c = 0; c < 64; c++) { float v = col[c * YPAD]; s += v; sq += v * v; }
        float mu = s * (1.f / 64.f);
        float var = sq * (1.f / 64.f) - mu * mu;
        float rstd = rsqrtf(var + 1e-5f);
        #pragma unroll 8
        for (int c = 0; c < 64; c++) col[c * YPAD] = (col[c * YPAD] - mu) * rstd;
    }
    __syncthreads();

    int warp = tid >> 5;        // 0..5
    int lane = tid & 31;
    int wg = warp % 3;          // column group of 64
    int pg = warp / 3;          // position half
    int jA = wg * 64 + lane;
    int jB = jA + 32;
    int p0 = pg * 32;
    const float* ybuf = (wg == 0) ? yq : yc;

    unsigned long long accA[16], accB[16];
    {
        unsigned long long bA = dup_f32(__ldg(&g_bc[jA]));
        unsigned long long bB = dup_f32(__ldg(&g_bc[jB]));
        #pragma unroll
        for (int i = 0; i < 16; i++) { accA[i] = bA; accB[i] = bB; }
    }

    #pragma unroll 2
    for (int c4 = 0; c4 < 16; c4++) {
        float4 wA4 = __ldg((const float4*)&g_Wt2[c4 * 768 + jA * 4]);
        float4 wB4 = __ldg((const float4*)&g_Wt2[c4 * 768 + jB * 4]);
        const float* wAp = (const float*)&wA4;
        const float* wBp = (const float*)&wB4;
        #pragma unroll
        for (int k = 0; k < 4; k++) {
            unsigned long long wa = dup_f32(wAp[k]);
            unsigned long long wb = dup_f32(wBp[k]);
            const float4* yp = (const float4*)&ybuf[(c4 * 4 + k) * YPAD + p0];
            #pragma unroll
            for (int m = 0; m < 8; m++) {
                float4 y4 = yp[m];
                unsigned long long y01 = f2_to_ull(y4.x, y4.y);
                unsigned long long y23 = f2_to_ull(y4.z, y4.w);
                ffma2(accA[2 * m],     y01, wa);
                ffma2(accA[2 * m + 1], y23, wa);
                ffma2(accB[2 * m],     y01, wb);
                ffma2(accB[2 * m + 1], y23, wb);
            }
        }
    }

    float* ob = g_qkvo + ((size_t)b * N + pb + p0) * 192;
    #pragma unroll
    for (int i = 0; i < 16; i++) {
        float2 a = ull_to_f2(accA[i]);
        float2 bv = ull_to_f2(accB[i]);
        ob[(size_t)(2 * i) * 192 + jA]     = a.x;
        ob[(size_t)(2 * i + 1) * 192 + jA] = a.y;
        ob[(size_t)(2 * i) * 192 + jB]     = bv.x;
        ob[(size_t)(2 * i + 1) * 192 + jB] = bv.y;
    }
}

// ---------------------------------------------------------------------------
// K3: attention gather. One warp per query, 8 adjacent queries per block.
// ---------------------------------------------------------------------------
__global__ void k_attn(const float* __restrict__ b_out,
                       float* __restrict__ out) {
    int lane = threadIdx.x & 31;
    int g = blockIdx.x * 8 + (threadIdx.x >> 5);   // 0..65535
    int b = g >> 14, n = g & (N - 1);
    int h = n >> 7, w = n & 127;

    const float* row = g_qkvo + (size_t)g * 192;
    float q0 = row[lane], q1 = row[32 + lane];

    const float* kvb = g_qkvo + (size_t)b * N * 192;
    int pp[9];
    float e[9];
    #pragma unroll
    for (int k = 0; k < 9; k++) {
        int di = k / 3 - 1, dj = k % 3 - 1;
        int hh = min(max(h + di, 0), H - 1);
        int ww = min(max(w + dj, 0), W - 1);
        pp[k] = hh * W + ww;
        const float* kr = kvb + (size_t)pp[k] * 192 + 64;
        float part = q0 * kr[lane] + q1 * kr[32 + lane];
        #pragma unroll
        for (int o = 1; o < 32; o <<= 1) part += __shfl_xor_sync(~0u, part, o);
        e[k] = part * 0.125f;
    }
    float m = e[0];
    #pragma unroll
    for (int k = 1; k < 9; k++) m = fmaxf(m, e[k]);
    float den = 0.f;
    #pragma unroll
    for (int k = 0; k < 9; k++) { e[k] = __expf(e[k] - m); den += e[k]; }
    float inv = 1.f / den;

    float o0 = 0.f, o1 = 0.f;
    #pragma unroll
    for (int k = 0; k < 9; k++) {
        const float* vr = kvb + (size_t)pp[k] * 192 + 128;
        float a = e[k] * inv;
        o0 += a * vr[lane];
        o1 += a * vr[32 + lane];
    }
    out[(size_t)g * OC + lane]      = o0 + __ldg(&b_out[lane]);
    out[(size_t)g * OC + 32 + lane] = o1 + __ldg(&b_out[lane + 32]);
}

// ---------------------------------------------------------------------------
// K4: tail — image sample, analytic fcoord sample, positional encoding.
// ---------------------------------------------------------------------------
__global__ void k_tail(const float* __restrict__ coords,
                       const float* __restrict__ image,
                       float* __restrict__ out) {
    int g = blockIdx.x * blockDim.x + threadIdx.x;
    if (g >= Bsz * N) return;
    int b = g >> 14;
    float y = coords[(size_t)g * 2 + 0];
    float x = coords[(size_t)g * 2 + 1];

    float ix = ((x + 1.f) * 256.f - 1.f) * 0.5f;
    float iy = ((y + 1.f) * 256.f - 1.f) * 0.5f;
    float x0f = floorf(ix), y0f = floorf(iy);
    float wx = ix - x0f, wy = iy - y0f;
    int x0 = (int)x0f, y0 = (int)y0f;
    const float* img = image + (size_t)b * 256 * 256;

    float ix2 = ((x + 1.f) * 128.f - 1.f) * 0.5f;
    float iy2 = ((y + 1.f) * 128.f - 1.f) * 0.5f;
    float x0f2 = floorf(ix2), y0f2 = floorf(iy2);
    float wx2 = ix2 - x0f2, wy2 = iy2 - y0f2;
    int x02 = (int)x0f2, y02 = (int)y0f2;

    float qin = 0.f, qcy = 0.f, qcx = 0.f;
    #pragma unroll
    for (int dy = 0; dy < 2; dy++) {
        #pragma unroll
        for (int dx = 0; dx < 2; dx++) {
            {
                int xc = x0 + dx, yc = y0 + dy;
                float wgt = (dx ? wx : 1.f - wx) * (dy ? wy : 1.f - wy);
                bool valid = (xc >= 0) && (xc < 256) && (yc >= 0) && (yc < 256);
                int xi = min(max(xc, 0), 255), yi = min(max(yc, 0), 255);
                qin += (valid ? wgt : 0.f) * img[yi * 256 + xi];
            }
            {
                int xc = x02 + dx, yc = y02 + dy;
                float wgt = (dx ? wx2 : 1.f - wx2) * (dy ? wy2 : 1.f - wy2);
                bool valid = (xc >= 0) && (xc < 128) && (yc >= 0) && (yc < 128);
                int xi = min(max(xc, 0), 127), yi = min(max(yc, 0), 127);
                float wv = valid ? wgt : 0.f;
                qcy += wv * (-1.f + (2.f * yi + 1.f) * (1.f / 128.f));
                qcx += wv * (-1.f + (2.f * xi + 1.f) * (1.f / 128.f));
            }
        }
    }

    float* o = out + (size_t)g * OC + 64;
    o[0] = qin;
    float cy = (qcy + 1.f) * 0.5f;
    float cx = (qcx + 1.f) * 0.5f;
    const float PI = 3.14159265358979323846f;
    #pragma unroll
    for (int k = 0; k < 6; k++) {
        float f = (float)(1 << k) * PI;
        float sy, cvy, sx, cvx;
        sincosf(cy * f, &sy, &cvy);
        sincosf(cx * f, &sx, &cvx);
        o[1 + k]          = sy;
        o[1 + 6 + k]      = sx;
        o[1 + 12 + k]     = cvy;
        o[1 + 12 + 6 + k] = cvx;
    }
}

extern "C" void kernel_launch(void* const* d_in, const int* in_sizes, int n_in,
                              void* d_out, int out_size) {
    const float* image   = (const float*)d_in[0];
    const float* latents = (const float*)d_in[1];
    const float* coords  = (const float*)d_in[2];
    const float* lnq_s   = (const float*)d_in[3];
    const float* lnq_b   = (const float*)d_in[4];
    const float* lnc_s   = (const float*)d_in[5];
    const float* lnc_b   = (const float*)d_in[6];
    const float* w_q     = (const float*)d_in[7];
    const float* w_kv    = (const float*)d_in[8];
    const float* w_out   = (const float*)d_in[9];
    const float* b_out   = (const float*)d_in[10];
    float* out = (float*)d_out;

    k_prep      <<<192, 64>>>(w_q, w_kv, w_out, lnq_s, lnq_b, lnc_s, lnc_b);
    k_transpose <<<1024, 256>>>(latents);
    k_sample_lat<<<8192, 256>>>(coords);
    k_qkvo      <<<1024, 192>>>();
    k_attn      <<<8192, 256>>>(b_out, out);
    k_tail      <<<256, 256>>>(coords, image, out);
}